// round 3
// baseline (speedup 1.0000x reference)
#include <cuda_runtime.h>
#include <cuda_bf16.h>
#include <mma.h>

using namespace nvcuda;

#define BATCH 8192
#define DIN   1024
#define DOUT  1024
#define NP    2048

#define LANCZOS_M 32

#define SPECTRAL_WEIGHT 0.1
#define DELTA_THRESHOLD 0.01

// ---------------- scratch (static __device__: allocation-free) ----------------
__device__ float g_F[(size_t)NP * NP];   // Fisher matrix, 16 MB (fits L2)
__device__ float g_q[2][NP];             // Lanczos vectors q_{j-1}, q_j (ping-pong)
__device__ float g_y[NP];                // y = F q_j
__device__ float g_alpha[64];
__device__ float g_beta[64];

// ---------------- init: normalized deterministic start vector ----------------
__global__ void init_kernel() {
  __shared__ float red[32];
  const int tid = threadIdx.x;         // 1024 threads, 2 elems each
  float v[2];
#pragma unroll
  for (int p = 0; p < 2; p++) {
    int j = tid + p * 1024;
    unsigned h = (unsigned)j * 2654435761u;
    h ^= h >> 16; h *= 2246822519u; h ^= h >> 13;
    v[p] = (float)(h & 0xFFFFFFu) * (1.0f / 16777216.0f) - 0.5f;
  }
  float s = v[0] * v[0] + v[1] * v[1];
#pragma unroll
  for (int o = 16; o; o >>= 1) s += __shfl_xor_sync(0xFFFFFFFFu, s, o);
  if ((tid & 31) == 0) red[tid >> 5] = s;
  __syncthreads();
  if (tid < 32) {
    float t = red[tid];
#pragma unroll
    for (int o = 16; o; o >>= 1) t += __shfl_xor_sync(0xFFFFFFFFu, t, o);
    if (tid == 0) red[0] = rsqrtf(t);
  }
  __syncthreads();
  const float inv = red[0];
#pragma unroll
  for (int p = 0; p < 2; p++) {
    int j = tid + p * 1024;
    g_q[0][j] = v[p] * inv;   // q_0 (unit norm)
    g_q[1][j] = 0.0f;         // q_{-1} = 0
  }
  if (tid < 64) { g_alpha[tid] = 0.0f; g_beta[tid] = 0.0f; }
}

// ---------------- GEMM1: out = X * W + b  (tf32 WMMA, 128x64 tiles) ----------
__global__ void gemm1_kernel(const float* __restrict__ X,
                             const float* __restrict__ W,
                             const float* __restrict__ bias,
                             float* __restrict__ out) {
  __shared__ float As[128][40];   // [m][k], row-major, ld=40
  __shared__ float Bs[32][72];    // [k][n], row-major, ld=72
  __shared__ float BiasS[16][64];

  const int tid  = threadIdx.x;
  const int M0   = blockIdx.y * 128;
  const int N0   = blockIdx.x * 64;
  const int warp = tid >> 5;
  const int wm   = warp >> 1;   // 0..3
  const int wn   = warp & 1;    // 0..1

  {
    int e = tid * 4;
    int r = e >> 6, c = e & 63;
    float4 bv = *reinterpret_cast<const float4*>(&bias[N0 + c]);
    *reinterpret_cast<float4*>(&BiasS[r][c]) = bv;
  }
  __syncthreads();

  wmma::fragment<wmma::accumulator, 16, 16, 8, float> acc[2][2];
#pragma unroll
  for (int i = 0; i < 2; i++)
#pragma unroll
    for (int j = 0; j < 2; j++)
      wmma::load_matrix_sync(acc[i][j], &BiasS[0][wn * 32 + j * 16], 64,
                             wmma::mem_row_major);

  const int kseg = (tid & 7) * 4;
  const int mb   = tid >> 3;
  const int nseg = (tid & 15) * 4;
  const int kb   = tid >> 4;

  for (int k0 = 0; k0 < DIN; k0 += 32) {
    __syncthreads();
#pragma unroll
    for (int p = 0; p < 4; p++) {
      int m = mb + p * 32;
      float4 v = *reinterpret_cast<const float4*>(&X[(size_t)(M0 + m) * DIN + k0 + kseg]);
      *reinterpret_cast<float4*>(&As[m][kseg]) = v;
    }
#pragma unroll
    for (int p = 0; p < 2; p++) {
      int k = kb + p * 16;
      float4 v = *reinterpret_cast<const float4*>(&W[(size_t)(k0 + k) * DOUT + N0 + nseg]);
      *reinterpret_cast<float4*>(&Bs[k][nseg]) = v;
    }
    __syncthreads();

#pragma unroll
    for (int kk = 0; kk < 32; kk += 8) {
      wmma::fragment<wmma::matrix_a, 16, 16, 8, wmma::precision::tf32, wmma::row_major> a[2];
      wmma::fragment<wmma::matrix_b, 16, 16, 8, wmma::precision::tf32, wmma::row_major> b[2];
#pragma unroll
      for (int i = 0; i < 2; i++) {
        wmma::load_matrix_sync(a[i], &As[wm * 32 + i * 16][kk], 40);
#pragma unroll
        for (int t = 0; t < a[i].num_elements; t++)
          a[i].x[t] = wmma::__float_to_tf32(a[i].x[t]);
      }
#pragma unroll
      for (int j = 0; j < 2; j++) {
        wmma::load_matrix_sync(b[j], &Bs[kk][wn * 32 + j * 16], 72);
#pragma unroll
        for (int t = 0; t < b[j].num_elements; t++)
          b[j].x[t] = wmma::__float_to_tf32(b[j].x[t]);
      }
#pragma unroll
      for (int i = 0; i < 2; i++)
#pragma unroll
        for (int j = 0; j < 2; j++)
          wmma::mma_sync(acc[i][j], a[i], b[j], acc[i][j]);
    }
  }

#pragma unroll
  for (int i = 0; i < 2; i++)
#pragma unroll
    for (int j = 0; j < 2; j++)
      wmma::store_matrix_sync(
          &out[(size_t)(M0 + wm * 32 + i * 16) * DOUT + N0 + wn * 32 + j * 16],
          acc[i][j], DOUT, wmma::mem_row_major);
}

// ---------------- GEMM2: F = G^T G / B  (bf16 WMMA syrk, upper tri only) -----
__global__ void gemm2_kernel(const float* __restrict__ G) {
  const int N0 = blockIdx.x * 128;
  const int M0 = blockIdx.y * 128;
  if (M0 > N0) return;  // symmetry: compute upper triangle, store both

  __shared__ __nv_bfloat16 As[32][136];
  __shared__ __nv_bfloat16 Bs[32][136];

  const int tid  = threadIdx.x;
  const int warp = tid >> 5;
  const int wm   = warp & 1;
  const int wn   = warp >> 1;

  wmma::fragment<wmma::accumulator, 16, 16, 16, float> acc[4][2];
#pragma unroll
  for (int i = 0; i < 4; i++)
#pragma unroll
    for (int j = 0; j < 2; j++)
      wmma::fill_fragment(acc[i][j], 0.0f);

  const int iseg = (tid & 31) * 4;
  const int kb   = tid >> 5;

  for (int k0 = 0; k0 < BATCH; k0 += 32) {
    __syncthreads();
#pragma unroll
    for (int p = 0; p < 4; p++) {
      int k = kb + p * 8;
      float4 va = *reinterpret_cast<const float4*>(&G[(size_t)(k0 + k) * NP + M0 + iseg]);
      As[k][iseg + 0] = __float2bfloat16(va.x);
      As[k][iseg + 1] = __float2bfloat16(va.y);
      As[k][iseg + 2] = __float2bfloat16(va.z);
      As[k][iseg + 3] = __float2bfloat16(va.w);
      float4 vb = *reinterpret_cast<const float4*>(&G[(size_t)(k0 + k) * NP + N0 + iseg]);
      Bs[k][iseg + 0] = __float2bfloat16(vb.x);
      Bs[k][iseg + 1] = __float2bfloat16(vb.y);
      Bs[k][iseg + 2] = __float2bfloat16(vb.z);
      Bs[k][iseg + 3] = __float2bfloat16(vb.w);
    }
    __syncthreads();

#pragma unroll
    for (int kk = 0; kk < 32; kk += 16) {
      wmma::fragment<wmma::matrix_a, 16, 16, 16, __nv_bfloat16, wmma::col_major> a[4];
      wmma::fragment<wmma::matrix_b, 16, 16, 16, __nv_bfloat16, wmma::row_major> b[2];
#pragma unroll
      for (int i = 0; i < 4; i++)
        wmma::load_matrix_sync(a[i], &As[kk][wm * 64 + i * 16], 136);
#pragma unroll
      for (int j = 0; j < 2; j++)
        wmma::load_matrix_sync(b[j], &Bs[kk][wn * 32 + j * 16], 136);
#pragma unroll
      for (int i = 0; i < 4; i++)
#pragma unroll
        for (int j = 0; j < 2; j++)
          wmma::mma_sync(acc[i][j], a[i], b[j], acc[i][j]);
    }
  }

  const float inv = 1.0f / (float)BATCH;
#pragma unroll
  for (int i = 0; i < 4; i++)
#pragma unroll
    for (int j = 0; j < 2; j++) {
#pragma unroll
      for (int t = 0; t < acc[i][j].num_elements; t++) acc[i][j].x[t] *= inv;
      int r0 = M0 + wm * 64 + i * 16;
      int c0 = N0 + wn * 32 + j * 16;
      wmma::store_matrix_sync(&g_F[(size_t)r0 * NP + c0], acc[i][j], NP,
                              wmma::mem_row_major);
      if (M0 != N0)
        wmma::store_matrix_sync(&g_F[(size_t)c0 * NP + r0], acc[i][j], NP,
                                wmma::mem_col_major);
    }
}

// ---------------- Lanczos matvec: y = F q_j,  alpha_j = q_j . y --------------
__global__ void lanczos_mv_kernel(int jbuf, int j) {
  __shared__ float xs[NP];
  __shared__ float salpha;
  const float* __restrict__ x = g_q[jbuf];
  const int tid = threadIdx.x;
  if (tid == 0) salpha = 0.0f;
  for (int i = tid; i < NP; i += blockDim.x) xs[i] = x[i];
  __syncthreads();

  const int warp = tid >> 5, lane = tid & 31;
  const int row = blockIdx.x * 8 + warp;
  const float* __restrict__ Frow = g_F + (size_t)row * NP;
  float acc = 0.0f;
  for (int k = lane; k < NP; k += 32) acc += Frow[k] * xs[k];
#pragma unroll
  for (int o = 16; o; o >>= 1) acc += __shfl_xor_sync(0xFFFFFFFFu, acc, o);

  if (lane == 0) {
    g_y[row] = acc;
    atomicAdd(&salpha, xs[row] * acc);   // smem pre-reduce (8 warps)
  }
  __syncthreads();
  if (tid == 0) atomicAdd(&g_alpha[j], salpha);
}

// ---------------- Lanczos update: w = y - a q_j - b q_{j-1}; q_{j+1}=w/||w|| -
__global__ void lanczos_update_kernel(int j) {
  __shared__ float red[32];
  const int tid = threadIdx.x;            // 1024 threads, 2 elems each
  const float alpha = g_alpha[j];
  const float bprev = (j > 0) ? g_beta[j - 1] : 0.0f;
  float* qc = g_q[j & 1];                 // q_j
  float* qp = g_q[(j & 1) ^ 1];           // q_{j-1}  (overwritten with q_{j+1})

  const int i0 = tid, i1 = tid + 1024;
  float w0 = g_y[i0] - alpha * qc[i0] - bprev * qp[i0];
  float w1 = g_y[i1] - alpha * qc[i1] - bprev * qp[i1];

  float s = w0 * w0 + w1 * w1;
#pragma unroll
  for (int o = 16; o; o >>= 1) s += __shfl_xor_sync(0xFFFFFFFFu, s, o);
  if ((tid & 31) == 0) red[tid >> 5] = s;
  __syncthreads();
  if (tid < 32) {
    float t = red[tid];
#pragma unroll
    for (int o = 16; o; o >>= 1) t += __shfl_xor_sync(0xFFFFFFFFu, t, o);
    if (tid == 0) red[0] = t;
  }
  __syncthreads();

  const float beta = sqrtf(red[0]);
  if (tid == 0) g_beta[j] = beta;
  const float inv = (beta > 0.0f) ? (1.0f / beta) : 0.0f;
  qp[i0] = w0 * inv;
  qp[i1] = w1 * inv;
}

// ---------------- tridiagonal smallest eigenvalue via Sturm bisection --------
__global__ void final_kernel(float* __restrict__ out) {
  double a[LANCZOS_M], b[LANCZOS_M];
  for (int i = 0; i < LANCZOS_M; i++) a[i] = (double)g_alpha[i];
  for (int i = 0; i < LANCZOS_M - 1; i++) b[i] = (double)g_beta[i];

  double lo = a[0], hi = a[0];
  for (int i = 0; i < LANCZOS_M; i++) {
    double r = (i > 0 ? fabs(b[i - 1]) : 0.0) +
               (i < LANCZOS_M - 1 ? fabs(b[i]) : 0.0);
    lo = fmin(lo, a[i] - r);
    hi = fmax(hi, a[i] + r);
  }
  for (int it = 0; it < 100; ++it) {
    double mid = 0.5 * (lo + hi);
    int cnt = 0;
    double d = a[0] - mid;
    if (d < 0.0) cnt++;
    for (int i = 1; i < LANCZOS_M; i++) {
      if (fabs(d) < 1e-300) d = -1e-300;
      d = a[i] - mid - b[i - 1] * b[i - 1] / d;
      if (d < 0.0) cnt++;
    }
    if (cnt >= 1) hi = mid; else lo = mid;
  }
  double lam1 = 0.5 * (lo + hi);
  double pen  = fmax(DELTA_THRESHOLD - lam1, 0.0);
  out[(size_t)BATCH * DOUT] = (float)(SPECTRAL_WEIGHT * pen);
}

// ---------------- launch ----------------
extern "C" void kernel_launch(void* const* d_in, const int* in_sizes, int n_in,
                              void* d_out, int out_size) {
  const float* X = (const float*)d_in[0];  // (8192, 1024)
  const float* G = (const float*)d_in[1];  // (8192, 2048)
  const float* W = (const float*)d_in[2];  // (1024, 1024)
  const float* b = (const float*)d_in[3];  // (1024,)
  float* out = (float*)d_out;              // 8192*1024 outputs + 1 scalar

  init_kernel<<<1, 1024>>>();
  gemm1_kernel<<<dim3(DOUT / 64, BATCH / 128), 256>>>(X, W, b, out);
  gemm2_kernel<<<dim3(NP / 128, NP / 128), 256>>>(G);

  for (int j = 0; j < LANCZOS_M; ++j) {
    lanczos_mv_kernel<<<NP / 8, 256>>>(j & 1, j);
    lanczos_update_kernel<<<1, 1024>>>(j);
  }

  final_kernel<<<1, 1>>>(out);
}

// round 6
// speedup vs baseline: 1.3130x; 1.3130x over previous
#include <cuda_runtime.h>
#include <cuda_bf16.h>
#include <mma.h>

using namespace nvcuda;

#define BATCH 8192
#define DIN   1024
#define DOUT  1024
#define NP    2048

#define LANCZOS_M 24

#define SPECTRAL_WEIGHT 0.1
#define DELTA_THRESHOLD 0.01

// ---------------- scratch (static __device__: allocation-free) ----------------
__device__ float g_F[(size_t)NP * NP];            // Fisher, 16 MB (L2-resident)
__device__ __nv_bfloat16 g_Gbf[(size_t)BATCH * NP]; // G in bf16, 32 MB
__device__ float g_q[2][NP];
__device__ float g_y[NP];
__device__ float g_alpha[64];
__device__ float g_beta[64];

// ---------------- cp.async helpers ----------------
__device__ __forceinline__ void cp16(void* s, const void* g) {
  unsigned a = (unsigned)__cvta_generic_to_shared(s);
  asm volatile("cp.async.cg.shared.global [%0], [%1], 16;\n" :: "r"(a), "l"(g));
}
__device__ __forceinline__ void cp_commit() {
  asm volatile("cp.async.commit_group;\n");
}
template <int N> __device__ __forceinline__ void cp_wait() {
  asm volatile("cp.async.wait_group %0;\n" :: "n"(N));
}

// ---------------- init: normalized deterministic start vector ----------------
__global__ void init_kernel() {
  __shared__ float red[32];
  const int tid = threadIdx.x;  // 1024 threads, 2 elems each
  float v[2];
#pragma unroll
  for (int p = 0; p < 2; p++) {
    int j = tid + p * 1024;
    unsigned h = (unsigned)j * 2654435761u;
    h ^= h >> 16; h *= 2246822519u; h ^= h >> 13;
    v[p] = (float)(h & 0xFFFFFFu) * (1.0f / 16777216.0f) - 0.5f;
  }
  float s = v[0] * v[0] + v[1] * v[1];
#pragma unroll
  for (int o = 16; o; o >>= 1) s += __shfl_xor_sync(0xFFFFFFFFu, s, o);
  if ((tid & 31) == 0) red[tid >> 5] = s;
  __syncthreads();
  if (tid < 32) {
    float t = red[tid];
#pragma unroll
    for (int o = 16; o; o >>= 1) t += __shfl_xor_sync(0xFFFFFFFFu, t, o);
    if (tid == 0) red[0] = rsqrtf(t);
  }
  __syncthreads();
  const float inv = red[0];
#pragma unroll
  for (int p = 0; p < 2; p++) {
    int j = tid + p * 1024;
    g_q[0][j] = v[p] * inv;
    g_q[1][j] = 0.0f;
  }
  if (tid < 64) { g_alpha[tid] = 0.0f; g_beta[tid] = 0.0f; }
}

// ---------------- convert G (fp32) -> g_Gbf (bf16) ----------------
__global__ void convert_kernel(const float* __restrict__ G) {
  size_t i = ((size_t)blockIdx.x * blockDim.x + threadIdx.x) * 4;
  float4 v = *reinterpret_cast<const float4*>(G + i);
  __nv_bfloat162 lo = __float22bfloat162_rn(make_float2(v.x, v.y));
  __nv_bfloat162 hi = __float22bfloat162_rn(make_float2(v.z, v.w));
  *reinterpret_cast<__nv_bfloat162*>(g_Gbf + i)     = lo;
  *reinterpret_cast<__nv_bfloat162*>(g_Gbf + i + 2) = hi;
}

// ---------------- GEMM1: out = X*W + b (tf32, 128x128 tile, 4-stage cp.async)
struct S1 {
  float As[4][128][20];   // [stage][m][k], k-tile 16, pad 20
  float Bs[4][16][132];   // [stage][k][n], pad 132
  float BiasS[16][128];
};
#define SMEM1 ((int)sizeof(S1))

__global__ void __launch_bounds__(256) gemm1_kernel(
    const float* __restrict__ X, const float* __restrict__ W,
    const float* __restrict__ bias, float* __restrict__ out) {
  extern __shared__ char smem_raw[];
  S1& s = *reinterpret_cast<S1*>(smem_raw);

  const int tid = threadIdx.x;
  const int M0 = blockIdx.y * 128;
  const int N0 = blockIdx.x * 128;
  const int warp = tid >> 5;
  const int wm = warp >> 1;  // 0..3 -> rows wm*32
  const int wn = warp & 1;   // 0..1 -> cols wn*64

  // bias tile (16 replicated rows -> loadable as accumulator fragment)
#pragma unroll
  for (int p = 0; p < 2; p++) {
    int e = (tid + p * 256) * 4;
    int r = e >> 7, c = e & 127;
    *reinterpret_cast<float4*>(&s.BiasS[r][c]) =
        *reinterpret_cast<const float4*>(&bias[N0 + c]);
  }

  // load one k-tile stage
  auto load_stage = [&](int st, int kt) {
    int k0 = kt * 16;
#pragma unroll
    for (int p = 0; p < 2; p++) {
      int c = tid + p * 256;            // A chunk: 512 total
      int row = c >> 2, col = (c & 3) * 4;
      cp16(&s.As[st][row][col], &X[(size_t)(M0 + row) * DIN + k0 + col]);
    }
#pragma unroll
    for (int p = 0; p < 2; p++) {
      int c = tid + p * 256;            // B chunk: 512 total
      int k = c >> 5, col = (c & 31) * 4;
      cp16(&s.Bs[st][k][col], &W[(size_t)(k0 + k) * DOUT + N0 + col]);
    }
    cp_commit();
  };

  load_stage(0, 0);
  load_stage(1, 1);
  load_stage(2, 2);
  __syncthreads();  // BiasS ready

  wmma::fragment<wmma::accumulator, 16, 16, 8, float> acc[2][4];
#pragma unroll
  for (int i = 0; i < 2; i++)
#pragma unroll
    for (int j = 0; j < 4; j++)
      wmma::load_matrix_sync(acc[i][j], &s.BiasS[0][wn * 64 + j * 16], 128,
                             wmma::mem_row_major);

  const int KT = DIN / 16;  // 64
  for (int kt = 0; kt < KT; kt++) {
    if (kt < KT - 2)      cp_wait<2>();
    else if (kt == KT - 2) cp_wait<1>();
    else                   cp_wait<0>();
    __syncthreads();

    const int st = kt & 3;
#pragma unroll
    for (int kk = 0; kk < 16; kk += 8) {
      wmma::fragment<wmma::matrix_a, 16, 16, 8, wmma::precision::tf32, wmma::row_major> a[2];
      wmma::fragment<wmma::matrix_b, 16, 16, 8, wmma::precision::tf32, wmma::row_major> b[4];
#pragma unroll
      for (int i = 0; i < 2; i++) {
        wmma::load_matrix_sync(a[i], &s.As[st][wm * 32 + i * 16][kk], 20);
#pragma unroll
        for (int t = 0; t < a[i].num_elements; t++)
          a[i].x[t] = wmma::__float_to_tf32(a[i].x[t]);
      }
#pragma unroll
      for (int j = 0; j < 4; j++) {
        wmma::load_matrix_sync(b[j], &s.Bs[st][kk][wn * 64 + j * 16], 132);
#pragma unroll
        for (int t = 0; t < b[j].num_elements; t++)
          b[j].x[t] = wmma::__float_to_tf32(b[j].x[t]);
      }
#pragma unroll
      for (int i = 0; i < 2; i++)
#pragma unroll
        for (int j = 0; j < 4; j++)
          wmma::mma_sync(acc[i][j], a[i], b[j], acc[i][j]);
    }

    if (kt + 3 < KT) load_stage((kt + 3) & 3, kt + 3);
  }

#pragma unroll
  for (int i = 0; i < 2; i++)
#pragma unroll
    for (int j = 0; j < 4; j++)
      wmma::store_matrix_sync(
          &out[(size_t)(M0 + wm * 32 + i * 16) * DOUT + N0 + wn * 64 + j * 16],
          acc[i][j], DOUT, wmma::mem_row_major);
}

// ---------------- GEMM2: F = G^T G / B (bf16 syrk, 128x128, 4-stage) --------
struct S2 {
  __nv_bfloat16 As[4][32][136];  // [stage][k][i] = Gbf[k0+k][M0+i]
  __nv_bfloat16 Bs[4][32][136];  // [stage][k][j] = Gbf[k0+k][N0+j]
};
#define SMEM2 ((int)sizeof(S2))

__global__ void __launch_bounds__(256) gemm2_kernel() {
  const int N0 = blockIdx.x * 128;
  const int M0 = blockIdx.y * 128;
  if (M0 > N0) return;  // symmetry

  extern __shared__ char smem_raw[];
  S2& s = *reinterpret_cast<S2*>(smem_raw);

  const int tid = threadIdx.x;
  const int warp = tid >> 5;
  const int wm = warp >> 1;
  const int wn = warp & 1;

  auto load_stage = [&](int st, int kt) {
    int k0 = kt * 32;
#pragma unroll
    for (int p = 0; p < 2; p++) {
      int c = tid + p * 256;            // 512 chunks (8 bf16 each)
      int k = c >> 4, col = (c & 15) * 8;
      cp16(&s.As[st][k][col], &g_Gbf[(size_t)(k0 + k) * NP + M0 + col]);
    }
#pragma unroll
    for (int p = 0; p < 2; p++) {
      int c = tid + p * 256;
      int k = c >> 4, col = (c & 15) * 8;
      cp16(&s.Bs[st][k][col], &g_Gbf[(size_t)(k0 + k) * NP + N0 + col]);
    }
    cp_commit();
  };

  load_stage(0, 0);
  load_stage(1, 1);
  load_stage(2, 2);

  wmma::fragment<wmma::accumulator, 16, 16, 16, float> acc[2][4];
#pragma unroll
  for (int i = 0; i < 2; i++)
#pragma unroll
    for (int j = 0; j < 4; j++)
      wmma::fill_fragment(acc[i][j], 0.0f);

  const int KT = BATCH / 32;  // 256
  for (int kt = 0; kt < KT; kt++) {
    if (kt < KT - 2)      cp_wait<2>();
    else if (kt == KT - 2) cp_wait<1>();
    else                   cp_wait<0>();
    __syncthreads();

    const int st = kt & 3;
#pragma unroll
    for (int kk = 0; kk < 32; kk += 16) {
      wmma::fragment<wmma::matrix_a, 16, 16, 16, __nv_bfloat16, wmma::col_major> a[2];
      wmma::fragment<wmma::matrix_b, 16, 16, 16, __nv_bfloat16, wmma::row_major> b[4];
#pragma unroll
      for (int i = 0; i < 2; i++)
        wmma::load_matrix_sync(a[i], &s.As[st][kk][wm * 32 + i * 16], 136);
#pragma unroll
      for (int j = 0; j < 4; j++)
        wmma::load_matrix_sync(b[j], &s.Bs[st][kk][wn * 64 + j * 16], 136);
#pragma unroll
      for (int i = 0; i < 2; i++)
#pragma unroll
        for (int j = 0; j < 4; j++)
          wmma::mma_sync(acc[i][j], a[i], b[j], acc[i][j]);
    }

    if (kt + 3 < KT) load_stage((kt + 3) & 3, kt + 3);
  }

  const float inv = 1.0f / (float)BATCH;
#pragma unroll
  for (int i = 0; i < 2; i++)
#pragma unroll
    for (int j = 0; j < 4; j++) {
#pragma unroll
      for (int t = 0; t < acc[i][j].num_elements; t++) acc[i][j].x[t] *= inv;
      int r0 = M0 + wm * 32 + i * 16;
      int c0 = N0 + wn * 64 + j * 16;
      wmma::store_matrix_sync(&g_F[(size_t)r0 * NP + c0], acc[i][j], NP,
                              wmma::mem_row_major);
      if (M0 != N0)
        wmma::store_matrix_sync(&g_F[(size_t)c0 * NP + r0], acc[i][j], NP,
                                wmma::mem_col_major);
    }
}

// ---------------- Lanczos matvec: y = F q_j, alpha_j = q_j . y (float4) -----
__global__ void lanczos_mv_kernel(int jbuf, int j) {
  __shared__ float4 xs[NP / 4];
  __shared__ float salpha;
  const float4* __restrict__ x4 = reinterpret_cast<const float4*>(g_q[jbuf]);
  const int tid = threadIdx.x;
  if (tid == 0) salpha = 0.0f;
  xs[tid]       = x4[tid];
  xs[tid + 256] = x4[tid + 256];
  __syncthreads();

  const int warp = tid >> 5, lane = tid & 31;
  const int row = blockIdx.x * 8 + warp;
  const float4* __restrict__ F4 =
      reinterpret_cast<const float4*>(g_F + (size_t)row * NP);
  float acc = 0.0f;
#pragma unroll
  for (int it = 0; it < 16; it++) {
    float4 f = F4[lane + it * 32];
    float4 v = xs[lane + it * 32];
    acc += f.x * v.x + f.y * v.y + f.z * v.z + f.w * v.w;
  }
#pragma unroll
  for (int o = 16; o; o >>= 1) acc += __shfl_xor_sync(0xFFFFFFFFu, acc, o);

  if (lane == 0) {
    g_y[row] = acc;
    atomicAdd(&salpha, reinterpret_cast<const float*>(xs)[row] * acc);
  }
  __syncthreads();
  if (tid == 0) atomicAdd(&g_alpha[j], salpha);
}

// ---------------- Lanczos update ----------------
__global__ void lanczos_update_kernel(int j) {
  __shared__ float red[32];
  const int tid = threadIdx.x;  // 1024 threads, 2 elems each
  const float alpha = g_alpha[j];
  const float bprev = (j > 0) ? g_beta[j - 1] : 0.0f;
  float* qc = g_q[j & 1];
  float* qp = g_q[(j & 1) ^ 1];

  const int i0 = tid, i1 = tid + 1024;
  float w0 = g_y[i0] - alpha * qc[i0] - bprev * qp[i0];
  float w1 = g_y[i1] - alpha * qc[i1] - bprev * qp[i1];

  float s = w0 * w0 + w1 * w1;
#pragma unroll
  for (int o = 16; o; o >>= 1) s += __shfl_xor_sync(0xFFFFFFFFu, s, o);
  if ((tid & 31) == 0) red[tid >> 5] = s;
  __syncthreads();
  if (tid < 32) {
    float t = red[tid];
#pragma unroll
    for (int o = 16; o; o >>= 1) t += __shfl_xor_sync(0xFFFFFFFFu, t, o);
    if (tid == 0) red[0] = t;
  }
  __syncthreads();

  const float beta = sqrtf(red[0]);
  if (tid == 0) g_beta[j] = beta;
  const float inv = (beta > 0.0f) ? (1.0f / beta) : 0.0f;
  qp[i0] = w0 * inv;
  qp[i1] = w1 * inv;
}

// ---------------- tridiagonal lambda_min via Sturm bisection ----------------
__global__ void final_kernel(float* __restrict__ out) {
  double a[LANCZOS_M], b[LANCZOS_M];
  for (int i = 0; i < LANCZOS_M; i++) a[i] = (double)g_alpha[i];
  for (int i = 0; i < LANCZOS_M - 1; i++) b[i] = (double)g_beta[i];

  double lo = a[0], hi = a[0];
  for (int i = 0; i < LANCZOS_M; i++) {
    double r = (i > 0 ? fabs(b[i - 1]) : 0.0) +
               (i < LANCZOS_M - 1 ? fabs(b[i]) : 0.0);
    lo = fmin(lo, a[i] - r);
    hi = fmax(hi, a[i] + r);
  }
  for (int it = 0; it < 100; ++it) {
    double mid = 0.5 * (lo + hi);
    int cnt = 0;
    double d = a[0] - mid;
    if (d < 0.0) cnt++;
    for (int i = 1; i < LANCZOS_M; i++) {
      if (fabs(d) < 1e-300) d = -1e-300;
      d = a[i] - mid - b[i - 1] * b[i - 1] / d;
      if (d < 0.0) cnt++;
    }
    if (cnt >= 1) hi = mid; else lo = mid;
  }
  double lam1 = 0.5 * (lo + hi);
  double pen  = fmax(DELTA_THRESHOLD - lam1, 0.0);
  out[(size_t)BATCH * DOUT] = (float)(SPECTRAL_WEIGHT * pen);
}

// ---------------- launch ----------------
extern "C" void kernel_launch(void* const* d_in, const int* in_sizes, int n_in,
                              void* d_out, int out_size) {
  const float* X = (const float*)d_in[0];  // (8192, 1024)
  const float* G = (const float*)d_in[1];  // (8192, 2048)
  const float* W = (const float*)d_in[2];  // (1024, 1024)
  const float* b = (const float*)d_in[3];  // (1024,)
  float* out = (float*)d_out;

  cudaFuncSetAttribute(gemm1_kernel, cudaFuncAttributeMaxDynamicSharedMemorySize, SMEM1);
  cudaFuncSetAttribute(gemm2_kernel, cudaFuncAttributeMaxDynamicSharedMemorySize, SMEM2);

  init_kernel<<<1, 1024>>>();
  convert_kernel<<<(BATCH * NP / 4) / 256, 256>>>(G);
  gemm1_kernel<<<dim3(DOUT / 128, BATCH / 128), 256, SMEM1>>>(X, W, b, out);
  gemm2_kernel<<<dim3(NP / 128, NP / 128), 256, SMEM2>>>();

  for (int j = 0; j < LANCZOS_M; ++j) {
    lanczos_mv_kernel<<<NP / 8, 256>>>(j & 1, j);
    lanczos_update_kernel<<<1, 1024>>>(j);
  }

  final_kernel<<<1, 1>>>(out);
}